// round 2
// baseline (speedup 1.0000x reference)
#include <cuda_runtime.h>
#include <cuda_bf16.h>

#define N_NODES 100000
#define N_EDGES 625000
#define IN_DIM 128
// W is [2, 256] row-major; class c row: first 128 cols for src-half, next 128 for dst-half.

// Scratch: per-node projections. A[n] = (dot(x[n], W[0,:128]), dot(x[n], W[1,:128]))
//          B[n] = (dot(x[n], W[0,128:]), dot(x[n], W[1,128:]))
__device__ float2 g_A[N_NODES];
__device__ float2 g_B[N_NODES];

// One warp per node. Each lane handles 4 consecutive features (one float4).
__global__ __launch_bounds__(256) void node_proj_kernel(
    const float4* __restrict__ x,   // [N_NODES * 32] float4 (128 floats/row)
    const float4* __restrict__ W)   // [2 * 64] float4 (256 floats/row)
{
    int gtid = blockIdx.x * blockDim.x + threadIdx.x;
    int node = gtid >> 5;
    int lane = gtid & 31;
    if (node >= N_NODES) return;

    float4 v = x[node * 32 + lane];

    // W row 0 (class 0): float4 index lane (src half), 32+lane (dst half)
    // W row 1 (class 1): float4 index 64+lane, 96+lane
    float4 w0s = __ldg(&W[lane]);
    float4 w0d = __ldg(&W[32 + lane]);
    float4 w1s = __ldg(&W[64 + lane]);
    float4 w1d = __ldg(&W[96 + lane]);

    float a0 = v.x * w0s.x + v.y * w0s.y + v.z * w0s.z + v.w * w0s.w;
    float a1 = v.x * w1s.x + v.y * w1s.y + v.z * w1s.z + v.w * w1s.w;
    float b0 = v.x * w0d.x + v.y * w0d.y + v.z * w0d.z + v.w * w0d.w;
    float b1 = v.x * w1d.x + v.y * w1d.y + v.z * w1d.z + v.w * w1d.w;

    #pragma unroll
    for (int off = 16; off > 0; off >>= 1) {
        a0 += __shfl_down_sync(0xFFFFFFFFu, a0, off);
        a1 += __shfl_down_sync(0xFFFFFFFFu, a1, off);
        b0 += __shfl_down_sync(0xFFFFFFFFu, b0, off);
        b1 += __shfl_down_sync(0xFFFFFFFFu, b1, off);
    }
    if (lane == 0) {
        g_A[node] = make_float2(a0, a1);
        g_B[node] = make_float2(b0, b1);
    }
}

// One thread per edge: two 8-byte L2-resident gathers + streaming index read / output write.
// NOTE: edge_index is int32 on device (JAX without x64 downcasts jnp.int64 -> int32).
__global__ __launch_bounds__(256) void edge_score_kernel(
    const int* __restrict__ ei,        // [2 * N_EDGES] int32
    const float* __restrict__ bias,    // [2]
    float2* __restrict__ out)          // [N_EDGES]
{
    int e = blockIdx.x * blockDim.x + threadIdx.x;
    if (e >= N_EDGES) return;

    int s = __ldg(&ei[e]);
    int d = __ldg(&ei[N_EDGES + e]);

    float2 A = g_A[s];
    float2 B = g_B[d];
    float b0 = __ldg(&bias[0]);
    float b1 = __ldg(&bias[1]);

    out[e] = make_float2(A.x + B.x + b0, A.y + B.y + b1);
}

extern "C" void kernel_launch(void* const* d_in, const int* in_sizes, int n_in,
                              void* d_out, int out_size)
{
    const float4* x  = (const float4*)d_in[0];   // [100000, 128] f32
    const int*    ei = (const int*)d_in[1];      // [2, 625000] i32
    const float4* W  = (const float4*)d_in[2];   // [2, 256] f32
    const float*  b  = (const float*)d_in[3];    // [2] f32
    float2*       out = (float2*)d_out;          // [625000, 2] f32

    // Kernel 1: per-node projections. 8 warps/block -> 12500 blocks.
    int warps_per_block = 256 / 32;
    int grid1 = (N_NODES + warps_per_block - 1) / warps_per_block;
    node_proj_kernel<<<grid1, 256>>>(x, W);

    // Kernel 2: per-edge gather + add.
    int grid2 = (N_EDGES + 255) / 256;
    edge_score_kernel<<<grid2, 256>>>(ei, b, out);
}

// round 3
// speedup vs baseline: 1.1764x; 1.1764x over previous
#include <cuda_runtime.h>
#include <cuda_bf16.h>

#define N_NODES 100000
#define N_EDGES 625000

// Combined per-node projection table: g_AB[n] = {a0+bias0, a1+bias1, b0, b1}
// where a_c = dot(x[n], W[c, 0:128]), b_c = dot(x[n], W[c, 128:256]).
__device__ float4 g_AB[N_NODES];

// 8 lanes per node, 4 nodes per warp.
// Lane l: group g = l>>3 (node within warp), w = l&7 (column slice).
// Each lane loads 4 independent float4s of x (MLP=4), computes 4 dot partials,
// 3-round butterfly over the 8-lane group (12 SHFL per warp = 3 per node).
__global__ __launch_bounds__(256) void node_proj_kernel(
    const float4* __restrict__ x,    // [N_NODES * 32] float4
    const float4* __restrict__ W,    // [2 * 64] float4 (class0: 0..63, class1: 64..127)
    const float*  __restrict__ bias) // [2]
{
    int gtid   = blockIdx.x * blockDim.x + threadIdx.x;
    int warpid = gtid >> 5;
    int lane   = gtid & 31;
    int g = lane >> 3;        // 0..3
    int w = lane & 7;         // 0..7
    int node = warpid * 4 + g;
    if (node >= N_NODES) return;

    // Data: 4 independent 16B loads per lane, covering columns w, w+8, w+16, w+24.
    const float4* xr = x + node * 32;
    float4 v0 = xr[w];
    float4 v1 = xr[w + 8];
    float4 v2 = xr[w + 16];
    float4 v3 = xr[w + 24];

    float a0 = 0.f, a1 = 0.f, b0 = 0.f, b1 = 0.f;
    #pragma unroll
    for (int j = 0; j < 4; j++) {
        float4 v = (j == 0) ? v0 : (j == 1) ? v1 : (j == 2) ? v2 : v3;
        int col = w + 8 * j;                    // float4 column index 0..31
        float4 wa0 = __ldg(&W[col]);            // class0 src half
        float4 wb0 = __ldg(&W[32 + col]);       // class0 dst half
        float4 wa1 = __ldg(&W[64 + col]);       // class1 src half
        float4 wb1 = __ldg(&W[96 + col]);       // class1 dst half
        a0 += v.x * wa0.x + v.y * wa0.y + v.z * wa0.z + v.w * wa0.w;
        b0 += v.x * wb0.x + v.y * wb0.y + v.z * wb0.z + v.w * wb0.w;
        a1 += v.x * wa1.x + v.y * wa1.y + v.z * wa1.z + v.w * wa1.w;
        b1 += v.x * wb1.x + v.y * wb1.y + v.z * wb1.z + v.w * wb1.w;
    }

    // Butterfly over the 8-lane group: offsets 4,2,1. Valid at w==0.
    #pragma unroll
    for (int off = 4; off > 0; off >>= 1) {
        a0 += __shfl_down_sync(0xFFFFFFFFu, a0, off);
        a1 += __shfl_down_sync(0xFFFFFFFFu, a1, off);
        b0 += __shfl_down_sync(0xFFFFFFFFu, b0, off);
        b1 += __shfl_down_sync(0xFFFFFFFFu, b1, off);
    }
    if (w == 0) {
        g_AB[node] = make_float4(a0 + __ldg(&bias[0]), a1 + __ldg(&bias[1]), b0, b1);
    }
}

// 4 edges per thread: int4 index loads, 8 independent 8B L2-resident gathers,
// two float4 output stores. Bias already folded into A.
__global__ __launch_bounds__(256) void edge_score_kernel(
    const int4* __restrict__ src4,   // ei[0:E] viewed as int4
    const int4* __restrict__ dst4,   // ei[E:2E] viewed as int4
    float4* __restrict__ out4)       // out viewed as float4 (2 edges per float4)
{
    int t = blockIdx.x * blockDim.x + threadIdx.x;
    if (t >= N_EDGES / 4) return;

    int4 s = __ldg(&src4[t]);
    int4 d = __ldg(&dst4[t]);

    const float2* AB = (const float2*)g_AB;   // A at 2*n, B at 2*n+1
    float2 A0 = AB[2 * s.x], A1 = AB[2 * s.y], A2 = AB[2 * s.z], A3 = AB[2 * s.w];
    float2 B0 = AB[2 * d.x + 1], B1 = AB[2 * d.y + 1], B2 = AB[2 * d.z + 1], B3 = AB[2 * d.w + 1];

    out4[2 * t]     = make_float4(A0.x + B0.x, A0.y + B0.y, A1.x + B1.x, A1.y + B1.y);
    out4[2 * t + 1] = make_float4(A2.x + B2.x, A2.y + B2.y, A3.x + B3.x, A3.y + B3.y);
}

extern "C" void kernel_launch(void* const* d_in, const int* in_sizes, int n_in,
                              void* d_out, int out_size)
{
    const float4* x    = (const float4*)d_in[0];            // [100000, 128] f32
    const int*    ei   = (const int*)d_in[1];               // [2, 625000] i32
    const float4* W    = (const float4*)d_in[2];            // [2, 256] f32
    const float*  b    = (const float*)d_in[3];             // [2] f32
    const int4*   src4 = (const int4*)ei;
    const int4*   dst4 = (const int4*)(ei + N_EDGES);
    float4*       out4 = (float4*)d_out;

    // Kernel 1: 4 nodes per warp, 8 warps per block -> 32 nodes/block.
    int grid1 = (N_NODES + 31) / 32;
    node_proj_kernel<<<grid1, 256>>>(x, W, b);

    // Kernel 2: 4 edges per thread.
    int grid2 = (N_EDGES / 4 + 255) / 256;
    edge_score_kernel<<<grid2, 256>>>(src4, dst4, out4);
}

// round 4
// speedup vs baseline: 1.2775x; 1.0860x over previous
#include <cuda_runtime.h>
#include <cuda_bf16.h>

#define N_NODES 100000
#define N_EDGES 625000

// Combined per-node projection table: g_AB[n] = {a0+bias0, a1+bias1, b0, b1}
__device__ float4 g_AB[N_NODES];

// 8 lanes per node, 4 nodes per warp; 3-round butterfly over 8-lane groups.
__global__ __launch_bounds__(256) void node_proj_kernel(
    const float4* __restrict__ x,    // [N_NODES * 32] float4
    const float4* __restrict__ W,    // [2 * 64] float4
    const float*  __restrict__ bias) // [2]
{
    int gtid   = blockIdx.x * blockDim.x + threadIdx.x;
    int warpid = gtid >> 5;
    int lane   = gtid & 31;
    int g = lane >> 3;
    int w = lane & 7;
    int node = warpid * 4 + g;

    if (node < N_NODES) {
        const float4* xr = x + node * 32;
        float4 v0 = xr[w];
        float4 v1 = xr[w + 8];
        float4 v2 = xr[w + 16];
        float4 v3 = xr[w + 24];

        float a0 = 0.f, a1 = 0.f, b0 = 0.f, b1 = 0.f;
        #pragma unroll
        for (int j = 0; j < 4; j++) {
            float4 v = (j == 0) ? v0 : (j == 1) ? v1 : (j == 2) ? v2 : v3;
            int col = w + 8 * j;
            float4 wa0 = __ldg(&W[col]);
            float4 wb0 = __ldg(&W[32 + col]);
            float4 wa1 = __ldg(&W[64 + col]);
            float4 wb1 = __ldg(&W[96 + col]);
            a0 += v.x * wa0.x + v.y * wa0.y + v.z * wa0.z + v.w * wa0.w;
            b0 += v.x * wb0.x + v.y * wb0.y + v.z * wb0.z + v.w * wb0.w;
            a1 += v.x * wa1.x + v.y * wa1.y + v.z * wa1.z + v.w * wa1.w;
            b1 += v.x * wb1.x + v.y * wb1.y + v.z * wb1.z + v.w * wb1.w;
        }

        #pragma unroll
        for (int off = 4; off > 0; off >>= 1) {
            a0 += __shfl_down_sync(0xFFFFFFFFu, a0, off);
            a1 += __shfl_down_sync(0xFFFFFFFFu, a1, off);
            b0 += __shfl_down_sync(0xFFFFFFFFu, b0, off);
            b1 += __shfl_down_sync(0xFFFFFFFFu, b1, off);
        }
        if (w == 0) {
            g_AB[node] = make_float4(a0 + __ldg(&bias[0]), a1 + __ldg(&bias[1]), b0, b1);
        }
    }

#if __CUDA_ARCH__ >= 900
    // Allow the dependent edge kernel to start its prologue as this kernel drains.
    cudaTriggerProgrammaticLaunchCompletion();
#endif
}

// 2 edges per thread. PDL: load indices first (independent of g_AB),
// then grid-dependency-sync, then gather. Bias folded into A.
__global__ __launch_bounds__(256) void edge_score_kernel(
    const int2* __restrict__ src2,   // ei[0:E] as int2
    const int2* __restrict__ dst2,   // ei[E:2E] as int2
    float4* __restrict__ out4)       // 2 edges per float4
{
    int t = blockIdx.x * blockDim.x + threadIdx.x;

    int2 s = make_int2(0, 0), d = make_int2(0, 0);
    bool valid = (t < N_EDGES / 2);
    if (valid) {
        s = __ldg(&src2[t]);
        d = __ldg(&dst2[t]);
    }

#if __CUDA_ARCH__ >= 900
    // Wait for node_proj to complete before touching g_AB.
    cudaGridDependencySynchronize();
#endif

    if (!valid) return;

    const float2* AB = (const float2*)g_AB;  // A at 2*n, B at 2*n+1
    float2 A0 = AB[2 * s.x],     A1 = AB[2 * s.y];
    float2 B0 = AB[2 * d.x + 1], B1 = AB[2 * d.y + 1];

    out4[t] = make_float4(A0.x + B0.x, A0.y + B0.y, A1.x + B1.x, A1.y + B1.y);
}

extern "C" void kernel_launch(void* const* d_in, const int* in_sizes, int n_in,
                              void* d_out, int out_size)
{
    const float4* x    = (const float4*)d_in[0];   // [100000, 128] f32
    const int*    ei   = (const int*)d_in[1];      // [2, 625000] i32
    const float4* W    = (const float4*)d_in[2];   // [2, 256] f32
    const float*  b    = (const float*)d_in[3];    // [2] f32
    const int2*   src2 = (const int2*)ei;
    const int2*   dst2 = (const int2*)(ei + N_EDGES);
    float4*       out4 = (float4*)d_out;

    // Kernel 1: per-node projections.
    int grid1 = (N_NODES + 31) / 32;
    node_proj_kernel<<<grid1, 256>>>(x, W, b);

    // Kernel 2: per-edge gather with programmatic dependent launch.
    int grid2 = (N_EDGES / 2 + 255) / 256;

    cudaLaunchConfig_t cfg = {};
    cfg.gridDim  = dim3((unsigned)grid2, 1, 1);
    cfg.blockDim = dim3(256, 1, 1);
    cfg.dynamicSmemBytes = 0;
    cfg.stream = 0;
    cudaLaunchAttribute attrs[1];
    attrs[0].id = cudaLaunchAttributeProgrammaticStreamSerialization;
    attrs[0].val.programmaticStreamSerializationAllowed = 1;
    cfg.attrs = attrs;
    cfg.numAttrs = 1;

    cudaError_t err = cudaLaunchKernelEx(&cfg, edge_score_kernel, src2, dst2, out4);
    if (err != cudaSuccess) {
        // Fallback: plain serialized launch (still correct).
        edge_score_kernel<<<grid2, 256>>>(src2, dst2, out4);
    }
}

// round 5
// speedup vs baseline: 1.4117x; 1.1050x over previous
#include <cuda_runtime.h>
#include <cuda_bf16.h>

#define N_NODES 100000
#define N_EDGES 625000

// Combined per-node projection table: g_AB[n] = {a0+bias0, a1+bias1, b0, b1}
__device__ float4 g_AB[N_NODES];

// 8 lanes per node-pair group, 4 groups per warp, 2 nodes per group -> 8 nodes/warp.
// Each lane issues 8 independent LDG.128 upfront (MLP=8); W regs shared across
// the two nodes of the group; 3 butterfly rounds per node (6 per group).
__global__ __launch_bounds__(256) void node_proj_kernel(
    const float4* __restrict__ x,    // [N_NODES * 32] float4
    const float4* __restrict__ W,    // [2 * 64] float4
    const float*  __restrict__ bias) // [2]
{
    int gtid   = blockIdx.x * blockDim.x + threadIdx.x;
    int warpid = gtid >> 5;
    int lane   = gtid & 31;
    int g = lane >> 3;        // group 0..3
    int w = lane & 7;         // lane-in-group 0..7

    int nodeA = warpid * 8 + g;        // first node of this group
    int nodeB = nodeA + 4;             // second node of this group
    bool va = (nodeA < N_NODES);
    bool vb = (nodeB < N_NODES);

    float4 u0, u1, u2, u3, v0, v1, v2, v3;
    u0 = u1 = u2 = u3 = v0 = v1 = v2 = v3 = make_float4(0.f, 0.f, 0.f, 0.f);
    if (va) {
        const float4* xr = x + nodeA * 32;
        u0 = xr[w]; u1 = xr[w + 8]; u2 = xr[w + 16]; u3 = xr[w + 24];
    }
    if (vb) {
        const float4* xr = x + nodeB * 32;
        v0 = xr[w]; v1 = xr[w + 8]; v2 = xr[w + 16]; v3 = xr[w + 24];
    }

    float ua0 = 0.f, ua1 = 0.f, ub0 = 0.f, ub1 = 0.f;   // node A accumulators
    float va0 = 0.f, va1 = 0.f, vb0 = 0.f, vb1 = 0.f;   // node B accumulators

    #pragma unroll
    for (int j = 0; j < 4; j++) {
        float4 u = (j == 0) ? u0 : (j == 1) ? u1 : (j == 2) ? u2 : u3;
        float4 v = (j == 0) ? v0 : (j == 1) ? v1 : (j == 2) ? v2 : v3;
        int col = w + 8 * j;
        float4 wa0 = __ldg(&W[col]);        // class0 src half
        float4 wb0 = __ldg(&W[32 + col]);   // class0 dst half
        float4 wa1 = __ldg(&W[64 + col]);   // class1 src half
        float4 wb1 = __ldg(&W[96 + col]);   // class1 dst half

        ua0 += u.x * wa0.x + u.y * wa0.y + u.z * wa0.z + u.w * wa0.w;
        ub0 += u.x * wb0.x + u.y * wb0.y + u.z * wb0.z + u.w * wb0.w;
        ua1 += u.x * wa1.x + u.y * wa1.y + u.z * wa1.z + u.w * wa1.w;
        ub1 += u.x * wb1.x + u.y * wb1.y + u.z * wb1.z + u.w * wb1.w;

        va0 += v.x * wa0.x + v.y * wa0.y + v.z * wa0.z + v.w * wa0.w;
        vb0 += v.x * wb0.x + v.y * wb0.y + v.z * wb0.z + v.w * wb0.w;
        va1 += v.x * wa1.x + v.y * wa1.y + v.z * wa1.z + v.w * wa1.w;
        vb1 += v.x * wb1.x + v.y * wb1.y + v.z * wb1.z + v.w * wb1.w;
    }

    #pragma unroll
    for (int off = 4; off > 0; off >>= 1) {
        ua0 += __shfl_down_sync(0xFFFFFFFFu, ua0, off);
        ua1 += __shfl_down_sync(0xFFFFFFFFu, ua1, off);
        ub0 += __shfl_down_sync(0xFFFFFFFFu, ub0, off);
        ub1 += __shfl_down_sync(0xFFFFFFFFu, ub1, off);
        va0 += __shfl_down_sync(0xFFFFFFFFu, va0, off);
        va1 += __shfl_down_sync(0xFFFFFFFFu, va1, off);
        vb0 += __shfl_down_sync(0xFFFFFFFFu, vb0, off);
        vb1 += __shfl_down_sync(0xFFFFFFFFu, vb1, off);
    }

    if (w == 0) {
        float bi0 = __ldg(&bias[0]);
        float bi1 = __ldg(&bias[1]);
        if (va) g_AB[nodeA] = make_float4(ua0 + bi0, ua1 + bi1, ub0, ub1);
        if (vb) g_AB[nodeB] = make_float4(va0 + bi0, va1 + bi1, vb0, vb1);
    }

#if __CUDA_ARCH__ >= 900
    cudaTriggerProgrammaticLaunchCompletion();
#endif
}

// 2 edges per thread. PDL: load indices first (independent of g_AB),
// then grid-dependency-sync, then gather. Bias folded into A.
__global__ __launch_bounds__(256) void edge_score_kernel(
    const int2* __restrict__ src2,   // ei[0:E] as int2
    const int2* __restrict__ dst2,   // ei[E:2E] as int2
    float4* __restrict__ out4)       // 2 edges per float4
{
    int t = blockIdx.x * blockDim.x + threadIdx.x;

    int2 s = make_int2(0, 0), d = make_int2(0, 0);
    bool valid = (t < N_EDGES / 2);
    if (valid) {
        s = __ldg(&src2[t]);
        d = __ldg(&dst2[t]);
    }

#if __CUDA_ARCH__ >= 900
    cudaGridDependencySynchronize();
#endif

    if (!valid) return;

    const float2* AB = (const float2*)g_AB;  // A at 2*n, B at 2*n+1
    float2 A0 = AB[2 * s.x],     A1 = AB[2 * s.y];
    float2 B0 = AB[2 * d.x + 1], B1 = AB[2 * d.y + 1];

    out4[t] = make_float4(A0.x + B0.x, A0.y + B0.y, A1.x + B1.x, A1.y + B1.y);
}

extern "C" void kernel_launch(void* const* d_in, const int* in_sizes, int n_in,
                              void* d_out, int out_size)
{
    const float4* x    = (const float4*)d_in[0];   // [100000, 128] f32
    const int*    ei   = (const int*)d_in[1];      // [2, 625000] i32
    const float4* W    = (const float4*)d_in[2];   // [2, 256] f32
    const float*  b    = (const float*)d_in[3];    // [2] f32
    const int2*   src2 = (const int2*)ei;
    const int2*   dst2 = (const int2*)(ei + N_EDGES);
    float4*       out4 = (float4*)d_out;

    // Kernel 1: 8 nodes per warp, 8 warps per block -> 64 nodes/block.
    int grid1 = (N_NODES + 63) / 64;
    node_proj_kernel<<<grid1, 256>>>(x, W, b);

    // Kernel 2: per-edge gather with programmatic dependent launch.
    int grid2 = (N_EDGES / 2 + 255) / 256;

    cudaLaunchConfig_t cfg = {};
    cfg.gridDim  = dim3((unsigned)grid2, 1, 1);
    cfg.blockDim = dim3(256, 1, 1);
    cfg.dynamicSmemBytes = 0;
    cfg.stream = 0;
    cudaLaunchAttribute attrs[1];
    attrs[0].id = cudaLaunchAttributeProgrammaticStreamSerialization;
    attrs[0].val.programmaticStreamSerializationAllowed = 1;
    cfg.attrs = attrs;
    cfg.numAttrs = 1;

    cudaError_t err = cudaLaunchKernelEx(&cfg, edge_score_kernel, src2, dst2, out4);
    if (err != cudaSuccess) {
        edge_score_kernel<<<grid2, 256>>>(src2, dst2, out4);
    }
}